// round 5
// baseline (speedup 1.0000x reference)
#include <cuda_runtime.h>

#define B  32
#define T  1024
#define D  512
#define KW 3

#define BM 64
#define BN 128
#define BK 16
#define NTHREADS 256

// Scratch (allowed: __device__ globals, no runtime allocation)
__device__ float g_buf1[(size_t)B * T * D];
__device__ float g_buf2[(size_t)B * T * D];
__device__ int   g_cum[B * T];

// ---------------- f32x2 packed-FMA helpers (Blackwell) ----------------
__device__ __forceinline__ unsigned long long pack2(float x, float y) {
    unsigned long long r;
    asm("mov.b64 %0, {%1, %2};" : "=l"(r) : "f"(x), "f"(y));
    return r;
}
__device__ __forceinline__ void fma2(unsigned long long& d,
                                     unsigned long long a,
                                     unsigned long long b) {
    asm("fma.rn.f32x2 %0, %1, %2, %0;" : "+l"(d) : "l"(a), "l"(b));
}
__device__ __forceinline__ float2 unpack2(unsigned long long v) {
    float2 r;
    asm("mov.b64 {%0, %1}, %2;" : "=f"(r.x), "=f"(r.y) : "l"(v));
    return r;
}

// ---------------- conv1d(k=3, SAME, per-batch pad) + bias + relu ----------------
// y[b,t,n] = relu( bias[n] + sum_{tap,c} x[b, t+tap-1, c] * w[tap, c, n] )
__global__ __launch_bounds__(NTHREADS, 2)
void conv_relu_kernel(const float* __restrict__ x, const float* __restrict__ w,
                      const float* __restrict__ bias, float* __restrict__ y) {
    __shared__ __align__(16) float Xs[BM + 2][BK];
    __shared__ __align__(16) float Ws[KW][BK][BN];

    const int n0   = blockIdx.x * BN;
    const int t0   = blockIdx.y * BM;
    const int b    = blockIdx.z;
    const int tid  = threadIdx.x;
    const int lane = tid & 31;
    const int warp = tid >> 5;
    const int m0   = warp * 8;   // 8 output rows per warp

    unsigned long long acc[8][2];
#pragma unroll
    for (int r = 0; r < 8; r++) { acc[r][0] = 0ull; acc[r][1] = 0ull; }

    const float4* xg = reinterpret_cast<const float4*>(x);
    const float4* wg = reinterpret_cast<const float4*>(w);

    for (int c0 = 0; c0 < D; c0 += BK) {
        // X tile: rows 0..BM+1 map to t = t0-1+row, zero outside [0,T)
        for (int f = tid; f < (BM + 2) * (BK / 4); f += NTHREADS) {
            int row = f >> 2;
            int c4  = f & 3;
            int t   = t0 - 1 + row;
            float4 v = make_float4(0.f, 0.f, 0.f, 0.f);
            if (t >= 0 && t < T)
                v = xg[(size_t)(b * T + t) * (D / 4) + (c0 >> 2) + c4];
            *reinterpret_cast<float4*>(&Xs[row][c4 * 4]) = v;
        }
        // W tile: [tap][kk][n]
#pragma unroll
        for (int f = tid; f < KW * BK * (BN / 4); f += NTHREADS) {
            int nn4 = f & 31;
            int kk  = (f >> 5) & (BK - 1);
            int k   = f >> 9;
            float4 v = wg[(size_t)(k * D + c0 + kk) * (D / 4) + (n0 >> 2) + nn4];
            *reinterpret_cast<float4*>(&Ws[k][kk][nn4 * 4]) = v;
        }
        __syncthreads();

#pragma unroll 4
        for (int kk = 0; kk < BK; kk++) {
            unsigned long long a2[10];
#pragma unroll
            for (int j = 0; j < 10; j++) {
                float av = Xs[m0 + j][kk];   // warp-uniform: LDS broadcast
                a2[j] = pack2(av, av);
            }
#pragma unroll
            for (int tap = 0; tap < KW; tap++) {
                const unsigned long long* bp =
                    reinterpret_cast<const unsigned long long*>(&Ws[tap][kk][lane * 4]);
                unsigned long long b01 = bp[0];
                unsigned long long b23 = bp[1];
#pragma unroll
                for (int r = 0; r < 8; r++) {
                    fma2(acc[r][0], a2[r + tap], b01);
                    fma2(acc[r][1], a2[r + tap], b23);
                }
            }
        }
        __syncthreads();
    }

    const int nc = n0 + lane * 4;
    const float4 bv = *reinterpret_cast<const float4*>(&bias[nc]);
#pragma unroll
    for (int r = 0; r < 8; r++) {
        float2 lo = unpack2(acc[r][0]);
        float2 hi = unpack2(acc[r][1]);
        float4 o;
        o.x = fmaxf(lo.x + bv.x, 0.f);
        o.y = fmaxf(lo.y + bv.y, 0.f);
        o.z = fmaxf(hi.x + bv.z, 0.f);
        o.w = fmaxf(hi.y + bv.w, 0.f);
        *reinterpret_cast<float4*>(
            &y[((size_t)(b * T + t0 + m0 + r)) * D + nc]) = o;
    }
}

// ---------------- LayerNorm over last dim (warp per row) ----------------
__global__ __launch_bounds__(256)
void ln_kernel(const float* __restrict__ x, const float* __restrict__ gw,
               const float* __restrict__ gb, float* __restrict__ y) {
    const int row  = blockIdx.x * 8 + (threadIdx.x >> 5);
    const int lane = threadIdx.x & 31;
    const float4* xr = reinterpret_cast<const float4*>(x) + (size_t)row * (D / 4);
    float4 v[4];
    float s = 0.f, sq = 0.f;
#pragma unroll
    for (int i = 0; i < 4; i++) {
        float4 t = xr[i * 32 + lane];
        v[i] = t;
        s  += t.x + t.y + t.z + t.w;
        sq += t.x * t.x + t.y * t.y + t.z * t.z + t.w * t.w;
    }
#pragma unroll
    for (int o = 16; o > 0; o >>= 1) {
        s  += __shfl_xor_sync(0xffffffffu, s, o);
        sq += __shfl_xor_sync(0xffffffffu, sq, o);
    }
    const float mu = s * (1.0f / D);
    const float rs = rsqrtf(sq * (1.0f / D) - mu * mu + 1e-5f);
    float4* yr = reinterpret_cast<float4*>(y) + (size_t)row * (D / 4);
    const float4* gv = reinterpret_cast<const float4*>(gw);
    const float4* bv = reinterpret_cast<const float4*>(gb);
#pragma unroll
    for (int i = 0; i < 4; i++) {
        float4 g = gv[i * 32 + lane], bb = bv[i * 32 + lane], t = v[i], o;
        o.x = (t.x - mu) * rs * g.x + bb.x;
        o.y = (t.y - mu) * rs * g.y + bb.y;
        o.z = (t.z - mu) * rs * g.z + bb.z;
        o.w = (t.w - mu) * rs * g.w + bb.w;
        yr[i * 32 + lane] = o;
    }
}

// ---------------- LayerNorm + linear(512->1), fused ----------------
__global__ __launch_bounds__(256)
void ln_linear_kernel(const float* __restrict__ x, const float* __restrict__ gw,
                      const float* __restrict__ gb, const float* __restrict__ lw,
                      const float* __restrict__ lb, float* __restrict__ dur_out) {
    const int row  = blockIdx.x * 8 + (threadIdx.x >> 5);
    const int lane = threadIdx.x & 31;
    const float4* xr = reinterpret_cast<const float4*>(x) + (size_t)row * (D / 4);
    float4 v[4];
    float s = 0.f, sq = 0.f;
#pragma unroll
    for (int i = 0; i < 4; i++) {
        float4 t = xr[i * 32 + lane];
        v[i] = t;
        s  += t.x + t.y + t.z + t.w;
        sq += t.x * t.x + t.y * t.y + t.z * t.z + t.w * t.w;
    }
#pragma unroll
    for (int o = 16; o > 0; o >>= 1) {
        s  += __shfl_xor_sync(0xffffffffu, s, o);
        sq += __shfl_xor_sync(0xffffffffu, sq, o);
    }
    const float mu = s * (1.0f / D);
    const float rs = rsqrtf(sq * (1.0f / D) - mu * mu + 1e-5f);
    const float4* gv = reinterpret_cast<const float4*>(gw);
    const float4* bv = reinterpret_cast<const float4*>(gb);
    const float4* wv = reinterpret_cast<const float4*>(lw);
    float dot = 0.f;
#pragma unroll
    for (int i = 0; i < 4; i++) {
        float4 g = gv[i * 32 + lane], bb = bv[i * 32 + lane];
        float4 w = wv[i * 32 + lane], t = v[i];
        dot += ((t.x - mu) * rs * g.x + bb.x) * w.x;
        dot += ((t.y - mu) * rs * g.y + bb.y) * w.y;
        dot += ((t.z - mu) * rs * g.z + bb.z) * w.z;
        dot += ((t.w - mu) * rs * g.w + bb.w) * w.w;
    }
#pragma unroll
    for (int o = 16; o > 0; o >>= 1)
        dot += __shfl_xor_sync(0xffffffffu, dot, o);
    if (lane == 0) dur_out[row] = dot + lb[0];
}

// ---------------- per-batch inclusive cumsum of durations ----------------
__global__ __launch_bounds__(T)
void cumsum_kernel(const int* __restrict__ dur, int* __restrict__ cum) {
    __shared__ int s[T];
    const int b = blockIdx.x, t = threadIdx.x;
    s[t] = dur[b * T + t];
    __syncthreads();
#pragma unroll
    for (int off = 1; off < T; off <<= 1) {
        int add = (t >= off) ? s[t - off] : 0;
        __syncthreads();
        s[t] += add;
        __syncthreads();
    }
    cum[b * T + t] = s[t];
}

// ---------------- length-regulation gather (block per output row) ----------------
__global__ __launch_bounds__(128)
void expand_kernel(const float* __restrict__ enc, const int* __restrict__ cum,
                   float* __restrict__ out, int max_len) {
    const int j    = blockIdx.x;
    const int b    = blockIdx.y;
    const int lane = threadIdx.x;   // 128 threads -> 128 float4 = 512 floats
    const int* c = cum + b * T;
    const int total = c[T - 1];
    float4 v = make_float4(0.f, 0.f, 0.f, 0.f);
    if (j < total) {
        int lo = 0, hi = T - 1;                 // searchsorted right
        while (lo < hi) {
            int mid = (lo + hi) >> 1;
            if (c[mid] > j) hi = mid; else lo = mid + 1;
        }
        v = reinterpret_cast<const float4*>(enc + (size_t)(b * T + lo) * D)[lane];
    }
    reinterpret_cast<float4*>(out + ((size_t)b * max_len + j) * D)[lane] = v;
}

extern "C" void kernel_launch(void* const* d_in, const int* in_sizes, int n_in,
                              void* d_out, int out_size) {
    const float* enc = (const float*)d_in[0];
    const int*   dur = (const int*)d_in[1];
    const float* w1  = (const float*)d_in[2];
    const float* b1  = (const float*)d_in[3];
    const float* g1  = (const float*)d_in[4];
    const float* be1 = (const float*)d_in[5];
    const float* w2  = (const float*)d_in[6];
    const float* b2  = (const float*)d_in[7];
    const float* g2  = (const float*)d_in[8];
    const float* be2 = (const float*)d_in[9];
    const float* lw  = (const float*)d_in[10];
    const float* lb  = (const float*)d_in[11];

    // max_len derived from out layout: out = [B, max_len, D] ++ [B, T]
    const int max_len = (out_size - B * T) / (B * D);

    float* out     = (float*)d_out;
    float* dur_out = out + (size_t)B * max_len * D;

    float* s1; cudaGetSymbolAddress((void**)&s1, g_buf1);
    float* s2; cudaGetSymbolAddress((void**)&s2, g_buf2);
    int*   cm; cudaGetSymbolAddress((void**)&cm, g_cum);

    dim3 cgrid(D / BN, T / BM, B);           // (4, 16, 32)
    conv_relu_kernel<<<cgrid, NTHREADS>>>(enc, w1, b1, s1);
    ln_kernel<<<B * T / 8, 256>>>(s1, g1, be1, s2);
    conv_relu_kernel<<<cgrid, NTHREADS>>>(s2, w2, b2, s1);
    ln_linear_kernel<<<B * T / 8, 256>>>(s1, g2, be2, lw, lb, dur_out);

    cumsum_kernel<<<B, T>>>(dur, cm);
    dim3 egrid(max_len, B);
    expand_kernel<<<egrid, 128>>>(enc, cm, out, max_len);
}

// round 8
// speedup vs baseline: 2.2674x; 2.2674x over previous
#include <cuda_runtime.h>
#include <cuda_bf16.h>
#include <cstdint>

#define B  32
#define T  1024
#define D  512
#define KW 3

// ---- conv GEMM tiles ----
#define BM 128
#define BN 128
#define BK 32
#define XS 40            // Xs row stride in bf16 (80B: conflict-free for ldmatrix)
#define WS 136           // Ws row stride in bf16 (272B: conflict-free for ldmatrix.trans)
#define CONV_THREADS 256

// dynamic smem plane offsets (bytes)
#define X_PLANE ((BM + 2) * XS * 2)        // 10400
#define W_PLANE (KW * BK * WS * 2)         // 26112
#define SM_XH 0
#define SM_XL (X_PLANE)
#define SM_WH (2 * X_PLANE)
#define SM_WL (2 * X_PLANE + W_PLANE)
#define SM_TOTAL (2 * X_PLANE + 2 * W_PLANE)   // 73024

// ---- scratch (no runtime allocation allowed) ----
__device__ float         g_conv[(size_t)B * T * D];    // fp32 conv output
__device__ __nv_bfloat16 g_xh1[(size_t)B * T * D];     // enc hi/lo
__device__ __nv_bfloat16 g_xl1[(size_t)B * T * D];
__device__ __nv_bfloat16 g_xh2[(size_t)B * T * D];     // LN1 out hi/lo
__device__ __nv_bfloat16 g_xl2[(size_t)B * T * D];
__device__ __nv_bfloat16 g_wh1[KW * D * D];            // weights hi/lo (native HIO)
__device__ __nv_bfloat16 g_wl1[KW * D * D];
__device__ __nv_bfloat16 g_wh2[KW * D * D];
__device__ __nv_bfloat16 g_wl2[KW * D * D];
__device__ int           g_cum[B * T];

__device__ __forceinline__ uint32_t smem_u32(const void* p) {
    uint32_t a;
    asm("{ .reg .u64 t; cvta.to.shared.u64 t, %1; cvt.u32.u64 %0, t; }" : "=r"(a) : "l"(p));
    return a;
}
__device__ __forceinline__ uint32_t pack_bf16x2(float x, float y) {
    __nv_bfloat162 p = __floats2bfloat162_rn(x, y);
    return reinterpret_cast<const unsigned&>(p);
}
// split one float into bf16 hi + bf16 lo
__device__ __forceinline__ void split1(float v, __nv_bfloat16& h, __nv_bfloat16& l) {
    h = __float2bfloat16_rn(v);
    l = __float2bfloat16_rn(v - __bfloat162float(h));
}

// ================= conv1d(k=3,SAME) + bias + relu, 3-term bf16 mma.sync ===========
// y = relu(bias + sum x*w), x = xh+xl, w = wh+wl, acc = xh*wh + xl*wh + xh*wl (fp32)
__global__ void __launch_bounds__(CONV_THREADS)
conv_mma_kernel(const __nv_bfloat16* __restrict__ xh,
                const __nv_bfloat16* __restrict__ xl,
                const __nv_bfloat16* __restrict__ wh,   // [tap][c][n]
                const __nv_bfloat16* __restrict__ wl,
                const float* __restrict__ bias,
                float* __restrict__ y) {
    extern __shared__ __align__(16) char smem[];

    const int tid  = threadIdx.x;
    const int lane = tid & 31;
    const int wid  = tid >> 5;
    const int wm   = wid >> 1;     // 0..3 -> m offset wm*32
    const int wn   = wid & 1;      // 0..1 -> n offset wn*64
    const int t0   = blockIdx.x * BM;
    const int n0   = blockIdx.y * BN;
    const int b    = blockIdx.z;

    float c[2][8][4];
#pragma unroll
    for (int mt = 0; mt < 2; mt++)
#pragma unroll
        for (int nt = 0; nt < 8; nt++)
#pragma unroll
            for (int i = 0; i < 4; i++) c[mt][nt][i] = 0.f;

    const uint32_t sb = smem_u32(smem);
    // ldmatrix lane address bases (bytes) for the hi planes
    const uint32_t a_lane = sb + SM_XH +
        (uint32_t)(((wm * 32 + (lane & 15)) * XS + (lane >> 4) * 8) * 2);
    const uint32_t b_lane = sb + SM_WH +
        (uint32_t)(((lane & 15) * WS + wn * 64 + (lane >> 4) * 8) * 2);

    for (int c0 = 0; c0 < D; c0 += BK) {
        if (c0) __syncthreads();
        // ---- X tiles: 130 rows x 32 bf16, row r <-> t=t0+r-1 (zero pad), hi+lo ----
#pragma unroll
        for (int p = 0; p < 2; p++) {
            const __nv_bfloat16* xp = p ? xl : xh;
            char* dst = smem + (p ? SM_XL : SM_XH);
#pragma unroll
            for (int i = 0; i < 3; i++) {
                int idx = tid + i * CONV_THREADS;      // 0..519 used
                if (idx < (BM + 2) * 4) {
                    int row = idx >> 2, u = idx & 3;
                    int t = t0 + row - 1;
                    uint4 v = make_uint4(0u, 0u, 0u, 0u);
                    if (t >= 0 && t < T)
                        v = *reinterpret_cast<const uint4*>(
                                xp + ((size_t)(b * T + t) * D + c0 + u * 8));
                    *reinterpret_cast<uint4*>(dst + (row * XS + u * 8) * 2) = v;
                }
            }
        }
        // ---- W tiles: [tap][k 0..31][n 0..127], hi+lo ----
#pragma unroll
        for (int p = 0; p < 2; p++) {
            const __nv_bfloat16* wp = p ? wl : wh;
            char* dst = smem + (p ? SM_WL : SM_WH);
#pragma unroll
            for (int i = 0; i < 6; i++) {
                int idx = tid + i * CONV_THREADS;      // 0..1535
                int r = idx >> 4, u = idx & 15;        // r = tap*32+k
                int tap = r >> 5, k = r & 31;
                uint4 v = *reinterpret_cast<const uint4*>(
                              wp + ((size_t)(tap * D + c0 + k) * D + n0 + u * 8));
                *reinterpret_cast<uint4*>(dst + (r * WS + u * 8) * 2) = v;
            }
        }
        __syncthreads();

#pragma unroll
        for (int tap = 0; tap < KW; tap++) {
#pragma unroll
            for (int ks = 0; ks < 2; ks++) {
                uint32_t ah[2][4], al[2][4];
#pragma unroll
                for (int mt = 0; mt < 2; mt++) {
                    uint32_t addr = a_lane + (uint32_t)((mt * 16 + tap) * XS * 2 + ks * 32);
                    asm volatile(
                        "ldmatrix.sync.aligned.m8n8.x4.shared.b16 {%0,%1,%2,%3}, [%4];"
                        : "=r"(ah[mt][0]), "=r"(ah[mt][1]), "=r"(ah[mt][2]), "=r"(ah[mt][3])
                        : "r"(addr));
                    asm volatile(
                        "ldmatrix.sync.aligned.m8n8.x4.shared.b16 {%0,%1,%2,%3}, [%4];"
                        : "=r"(al[mt][0]), "=r"(al[mt][1]), "=r"(al[mt][2]), "=r"(al[mt][3])
                        : "r"(addr + (uint32_t)X_PLANE));
                }
                uint32_t bh[4][4], bl[4][4];
#pragma unroll
                for (int q = 0; q < 4; q++) {
                    uint32_t addr = b_lane +
                        (uint32_t)((tap * 32 + ks * 16) * WS * 2 + q * 32);
                    asm volatile(
                        "ldmatrix.sync.aligned.m8n8.x4.trans.shared.b16 {%0,%1,%2,%3}, [%4];"
                        : "=r"(bh[q][0]), "=r"(bh[q][1]), "=r"(bh[q][2]), "=r"(bh[q][3])
                        : "r"(addr));
                    asm volatile(
                        "ldmatrix.sync.aligned.m8n8.x4.trans.shared.b16 {%0,%1,%2,%3}, [%4];"
                        : "=r"(bl[q][0]), "=r"(bl[q][1]), "=r"(bl[q][2]), "=r"(bl[q][3])
                        : "r"(addr + (uint32_t)W_PLANE));
                }
#pragma unroll
                for (int mt = 0; mt < 2; mt++)
#pragma unroll
                    for (int nt = 0; nt < 8; nt++) {
                        int q = nt >> 1, h = (nt & 1) * 2;
#define MMA_ACC(A0,A1,A2,A3,B0,B1)                                             \
                        asm volatile(                                          \
                            "mma.sync.aligned.m16n8k16.row.col.f32.bf16.bf16.f32 " \
                            "{%0,%1,%2,%3}, {%4,%5,%6,%7}, {%8,%9}, {%0,%1,%2,%3};" \
                            : "+f"(c[mt][nt][0]), "+f"(c[mt][nt][1]),          \
                              "+f"(c[mt][nt][2]), "+f"(c[mt][nt][3])           \
                            : "r"(A0), "r"(A1), "r"(A2), "r"(A3), "r"(B0), "r"(B1))
                        MMA_ACC(ah[mt][0], ah[mt][1], ah[mt][2], ah[mt][3],
                                bh[q][h], bh[q][h + 1]);
                        MMA_ACC(al[mt][0], al[mt][1], al[mt][2], al[mt][3],
                                bh[q][h], bh[q][h + 1]);
                        MMA_ACC(ah[mt][0], ah[mt][1], ah[mt][2], ah[mt][3],
                                bl[q][h], bl[q][h + 1]);
#undef MMA_ACC
                    }
            }
        }
    }

    // ---- epilogue: bias + relu, fp32 store ----
    const int gid = lane >> 2, tig = lane & 3;
#pragma unroll
    for (int mt = 0; mt < 2; mt++) {
        int row0 = t0 + wm * 32 + mt * 16 + gid;
#pragma unroll
        for (int nt = 0; nt < 8; nt++) {
            int col = n0 + wn * 64 + nt * 8 + tig * 2;
            float bx = bias[col], by = bias[col + 1];
            float2 o0, o1;
            o0.x = fmaxf(c[mt][nt][0] + bx, 0.f);
            o0.y = fmaxf(c[mt][nt][1] + by, 0.f);
            o1.x = fmaxf(c[mt][nt][2] + bx, 0.f);
            o1.y = fmaxf(c[mt][nt][3] + by, 0.f);
            *reinterpret_cast<float2*>(y + ((size_t)(b * T + row0)) * D + col) = o0;
            *reinterpret_cast<float2*>(y + ((size_t)(b * T + row0 + 8)) * D + col) = o1;
        }
    }
}

// ================= fp32 -> bf16 hi/lo split =================
__global__ void __launch_bounds__(256)
cvt_split_kernel(const float4* __restrict__ x, uint2* __restrict__ hi,
                 uint2* __restrict__ lo, int n4) {
    int i = blockIdx.x * 256 + threadIdx.x;
    if (i < n4) {
        float4 v = x[i];
        __nv_bfloat16 hx, lx, hy, ly, hz, lz, hw, lw;
        split1(v.x, hx, lx); split1(v.y, hy, ly);
        split1(v.z, hz, lz); split1(v.w, hw, lw);
        __nv_bfloat162 h0 = {hx, hy}, h1 = {hz, hw};
        __nv_bfloat162 l0 = {lx, ly}, l1 = {lz, lw};
        uint2 oh, ol;
        oh.x = reinterpret_cast<const unsigned&>(h0);
        oh.y = reinterpret_cast<const unsigned&>(h1);
        ol.x = reinterpret_cast<const unsigned&>(l0);
        ol.y = reinterpret_cast<const unsigned&>(l1);
        hi[i] = oh;
        lo[i] = ol;
    }
}

// ================= LayerNorm (fp32 in) -> bf16 hi/lo out =================
__global__ void __launch_bounds__(256)
ln_split_kernel(const float* __restrict__ x, const float* __restrict__ gw,
                const float* __restrict__ gb, __nv_bfloat16* __restrict__ yh,
                __nv_bfloat16* __restrict__ yl) {
    const int row  = blockIdx.x * 8 + (threadIdx.x >> 5);
    const int lane = threadIdx.x & 31;
    const float4* xr = reinterpret_cast<const float4*>(x) + (size_t)row * (D / 4);
    float4 v[4];
    float s = 0.f, sq = 0.f;
#pragma unroll
    for (int i = 0; i < 4; i++) {
        float4 t = xr[i * 32 + lane];
        v[i] = t;
        s  += t.x + t.y + t.z + t.w;
        sq += t.x * t.x + t.y * t.y + t.z * t.z + t.w * t.w;
    }
#pragma unroll
    for (int o = 16; o > 0; o >>= 1) {
        s  += __shfl_xor_sync(0xffffffffu, s, o);
        sq += __shfl_xor_sync(0xffffffffu, sq, o);
    }
    const float mu = s * (1.0f / D);
    const float rs = rsqrtf(sq * (1.0f / D) - mu * mu + 1e-5f);
    const float4* gv = reinterpret_cast<const float4*>(gw);
    const float4* bv = reinterpret_cast<const float4*>(gb);
    uint2* yhr = reinterpret_cast<uint2*>(yh + (size_t)row * D);
    uint2* ylr = reinterpret_cast<uint2*>(yl + (size_t)row * D);
#pragma unroll
    for (int i = 0; i < 4; i++) {
        float4 g = gv[i * 32 + lane], bb = bv[i * 32 + lane], t = v[i];
        float4 o;
        o.x = (t.x - mu) * rs * g.x + bb.x;
        o.y = (t.y - mu) * rs * g.y + bb.y;
        o.z = (t.z - mu) * rs * g.z + bb.z;
        o.w = (t.w - mu) * rs * g.w + bb.w;
        __nv_bfloat16 hx, lx, hy, ly, hz, lz, hw, lw;
        split1(o.x, hx, lx); split1(o.y, hy, ly);
        split1(o.z, hz, lz); split1(o.w, hw, lw);
        __nv_bfloat162 h0 = {hx, hy}, h1 = {hz, hw};
        __nv_bfloat162 l0 = {lx, ly}, l1 = {lz, lw};
        uint2 oh, ol;
        oh.x = reinterpret_cast<const unsigned&>(h0);
        oh.y = reinterpret_cast<const unsigned&>(h1);
        ol.x = reinterpret_cast<const unsigned&>(l0);
        ol.y = reinterpret_cast<const unsigned&>(l1);
        yhr[i * 32 + lane] = oh;
        ylr[i * 32 + lane] = ol;
    }
}

// ================= LayerNorm + linear(512->1) fused =================
__global__ void __launch_bounds__(256)
ln_linear_kernel(const float* __restrict__ x, const float* __restrict__ gw,
                 const float* __restrict__ gb, const float* __restrict__ lw,
                 const float* __restrict__ lb, float* __restrict__ dur_out) {
    const int row  = blockIdx.x * 8 + (threadIdx.x >> 5);
    const int lane = threadIdx.x & 31;
    const float4* xr = reinterpret_cast<const float4*>(x) + (size_t)row * (D / 4);
    float4 v[4];
    float s = 0.f, sq = 0.f;
#pragma unroll
    for (int i = 0; i < 4; i++) {
        float4 t = xr[i * 32 + lane];
        v[i] = t;
        s  += t.x + t.y + t.z + t.w;
        sq += t.x * t.x + t.y * t.y + t.z * t.z + t.w * t.w;
    }
#pragma unroll
    for (int o = 16; o > 0; o >>= 1) {
        s  += __shfl_xor_sync(0xffffffffu, s, o);
        sq += __shfl_xor_sync(0xffffffffu, sq, o);
    }
    const float mu = s * (1.0f / D);
    const float rs = rsqrtf(sq * (1.0f / D) - mu * mu + 1e-5f);
    const float4* gv = reinterpret_cast<const float4*>(gw);
    const float4* bv = reinterpret_cast<const float4*>(gb);
    const float4* wv = reinterpret_cast<const float4*>(lw);
    float dot = 0.f;
#pragma unroll
    for (int i = 0; i < 4; i++) {
        float4 g = gv[i * 32 + lane], bb = bv[i * 32 + lane];
        float4 w = wv[i * 32 + lane], t = v[i];
        dot += ((t.x - mu) * rs * g.x + bb.x) * w.x;
        dot += ((t.y - mu) * rs * g.y + bb.y) * w.y;
        dot += ((t.z - mu) * rs * g.z + bb.z) * w.z;
        dot += ((t.w - mu) * rs * g.w + bb.w) * w.w;
    }
#pragma unroll
    for (int o = 16; o > 0; o >>= 1)
        dot += __shfl_xor_sync(0xffffffffu, dot, o);
    if (lane == 0) dur_out[row] = dot + lb[0];
}

// ================= per-batch inclusive cumsum =================
__global__ void __launch_bounds__(T)
cumsum_kernel(const int* __restrict__ dur, int* __restrict__ cum) {
    __shared__ int s[T];
    const int b = blockIdx.x, t = threadIdx.x;
    s[t] = dur[b * T + t];
    __syncthreads();
#pragma unroll
    for (int off = 1; off < T; off <<= 1) {
        int add = (t >= off) ? s[t - off] : 0;
        __syncthreads();
        s[t] += add;
        __syncthreads();
    }
    cum[b * T + t] = s[t];
}

// ================= length-regulation gather =================
__global__ void __launch_bounds__(128)
expand_kernel(const float* __restrict__ enc, const int* __restrict__ cum,
              float* __restrict__ out, int max_len) {
    const int j    = blockIdx.x;
    const int b    = blockIdx.y;
    const int lane = threadIdx.x;
    const int* c = cum + b * T;
    const int total = c[T - 1];
    float4 v = make_float4(0.f, 0.f, 0.f, 0.f);
    if (j < total) {
        int lo = 0, hi = T - 1;
        while (lo < hi) {
            int mid = (lo + hi) >> 1;
            if (c[mid] > j) hi = mid; else lo = mid + 1;
        }
        v = reinterpret_cast<const float4*>(enc + (size_t)(b * T + lo) * D)[lane];
    }
    reinterpret_cast<float4*>(out + ((size_t)b * max_len + j) * D)[lane] = v;
}

extern "C" void kernel_launch(void* const* d_in, const int* in_sizes, int n_in,
                              void* d_out, int out_size) {
    const float* enc = (const float*)d_in[0];
    const int*   dur = (const int*)d_in[1];
    const float* w1  = (const float*)d_in[2];
    const float* b1  = (const float*)d_in[3];
    const float* g1  = (const float*)d_in[4];
    const float* be1 = (const float*)d_in[5];
    const float* w2  = (const float*)d_in[6];
    const float* b2  = (const float*)d_in[7];
    const float* g2  = (const float*)d_in[8];
    const float* be2 = (const float*)d_in[9];
    const float* lw  = (const float*)d_in[10];
    const float* lb  = (const float*)d_in[11];

    const int max_len = (out_size - B * T) / (B * D);
    float* out     = (float*)d_out;
    float* dur_out = out + (size_t)B * max_len * D;

    float* cbuf;        cudaGetSymbolAddress((void**)&cbuf, g_conv);
    __nv_bfloat16 *xh1, *xl1, *xh2, *xl2, *wh1, *wl1, *wh2, *wl2;
    cudaGetSymbolAddress((void**)&xh1, g_xh1);
    cudaGetSymbolAddress((void**)&xl1, g_xl1);
    cudaGetSymbolAddress((void**)&xh2, g_xh2);
    cudaGetSymbolAddress((void**)&xl2, g_xl2);
    cudaGetSymbolAddress((void**)&wh1, g_wh1);
    cudaGetSymbolAddress((void**)&wl1, g_wl1);
    cudaGetSymbolAddress((void**)&wh2, g_wh2);
    cudaGetSymbolAddress((void**)&wl2, g_wl2);
    int* cm;            cudaGetSymbolAddress((void**)&cm, g_cum);

    cudaFuncSetAttribute(conv_mma_kernel,
                         cudaFuncAttributeMaxDynamicSharedMemorySize, SM_TOTAL);

    // hi/lo splits: enc + both weight tensors (native layouts)
    const int nx4 = (B * T * D) / 4;
    cvt_split_kernel<<<nx4 / 256, 256>>>((const float4*)enc, (uint2*)xh1, (uint2*)xl1, nx4);
    const int nw4 = (KW * D * D) / 4;
    cvt_split_kernel<<<(nw4 + 255) / 256, 256>>>((const float4*)w1, (uint2*)wh1, (uint2*)wl1, nw4);
    cvt_split_kernel<<<(nw4 + 255) / 256, 256>>>((const float4*)w2, (uint2*)wh2, (uint2*)wl2, nw4);

    dim3 cgrid(T / BM, D / BN, B);   // (8, 4, 32)
    conv_mma_kernel<<<cgrid, CONV_THREADS, SM_TOTAL>>>(xh1, xl1, wh1, wl1, b1, cbuf);
    ln_split_kernel<<<B * T / 8, 256>>>(cbuf, g1, be1, xh2, xl2);
    conv_mma_kernel<<<cgrid, CONV_THREADS, SM_TOTAL>>>(xh2, xl2, wh2, wl2, b2, cbuf);
    ln_linear_kernel<<<B * T / 8, 256>>>(cbuf, g2, be2, lw, lb, dur_out);

    cumsum_kernel<<<B, T>>>(dur, cm);
    dim3 egrid(max_len, B);
    expand_kernel<<<egrid, 128>>>(enc, cm, out, max_len);
}

// round 9
// speedup vs baseline: 3.2696x; 1.4420x over previous
#include <cuda_runtime.h>
#include <cuda_fp16.h>
#include <cstdint>

#define B  32
#define T  1024
#define D  512
#define KW 3

// ---- conv GEMM tiles ----
#define BM 128
#define BN 128
#define BK 32
#define XS 40            // Xs row stride in fp16 (80B: conflict-free for ldmatrix)
#define WS 136           // Ws row stride in fp16 (272B: conflict-free for ldmatrix.trans)
#define CONV_THREADS 256
#define NCHUNK (D / BK)  // 16

// dynamic smem: two stages, each = [XH plane][XL plane][W plane]
#define X_PLANE ((BM + 2) * XS * 2)          // 10400 B
#define W_PLANE (KW * BK * WS * 2)           // 26112 B
#define STAGE   (2 * X_PLANE + W_PLANE)      // 46912 B
#define SM_TOTAL (2 * STAGE)                 // 93824 B

// ---- scratch (no runtime allocation allowed) ----
__device__ float  g_conv[(size_t)B * T * D];    // fp32 conv output
__device__ __half g_xh1[(size_t)B * T * D];     // enc hi/lo (fp16 exact split)
__device__ __half g_xl1[(size_t)B * T * D];
__device__ __half g_xh2[(size_t)B * T * D];     // LN1 out hi/lo
__device__ __half g_xl2[(size_t)B * T * D];
__device__ __half g_w1h[KW * D * D];            // weights fp16 (native HIO)
__device__ __half g_w2h[KW * D * D];
__device__ int    g_cum[B * T];

__device__ __forceinline__ uint32_t smem_u32(const void* p) {
    uint32_t a;
    asm("{ .reg .u64 t; cvta.to.shared.u64 t, %1; cvt.u32.u64 %0, t; }" : "=r"(a) : "l"(p));
    return a;
}
__device__ __forceinline__ void split1h(float v, __half& h, __half& l) {
    h = __float2half_rn(v);
    l = __float2half_rn(v - __half2float(h));
}
__device__ __forceinline__ void cp16(uint32_t dst, const void* src, int szbytes) {
    asm volatile("cp.async.cg.shared.global [%0], [%1], 16, %2;"
                 :: "r"(dst), "l"(src), "r"(szbytes));
}

// ================= conv1d(k=3,SAME) + bias + relu, fp16 2-term mma.sync ===========
// x = xh + xl (exact fp16 split), w fp16; acc = xh*w + xl*w in fp32.
__global__ void __launch_bounds__(CONV_THREADS)
conv_mma_kernel(const __half* __restrict__ xh,
                const __half* __restrict__ xl,
                const __half* __restrict__ w,   // [tap][c][n]
                const float* __restrict__ bias,
                float* __restrict__ y) {
    extern __shared__ __align__(16) char smem[];

    const int tid  = threadIdx.x;
    const int lane = tid & 31;
    const int wid  = tid >> 5;
    const int wm   = wid >> 1;     // 0..3 -> m offset wm*32
    const int wn   = wid & 1;      // 0..1 -> n offset wn*64
    const int t0   = blockIdx.x * BM;
    const int n0   = blockIdx.y * BN;
    const int b    = blockIdx.z;

    float c[2][8][4];
#pragma unroll
    for (int mt = 0; mt < 2; mt++)
#pragma unroll
        for (int nt = 0; nt < 8; nt++)
#pragma unroll
            for (int i = 0; i < 4; i++) c[mt][nt][i] = 0.f;

    const uint32_t sb = smem_u32(smem);
    const uint32_t a_off = (uint32_t)(((wm * 32 + (lane & 15)) * XS + (lane >> 4) * 8) * 2);
    const uint32_t b_off = (uint32_t)(2 * X_PLANE +
                                      ((lane & 15) * WS + wn * 64 + (lane >> 4) * 8) * 2);

    // ---- async tile loader for chunk c0 into stage st ----
    auto load_chunk = [&](int st, int c0) {
        const uint32_t stb = sb + (uint32_t)(st * STAGE);
        // X planes (hi, lo): 520 16B vectors each
#pragma unroll
        for (int p = 0; p < 2; p++) {
            const __half* xp = p ? xl : xh;
            const uint32_t pb = stb + (uint32_t)(p * X_PLANE);
#pragma unroll
            for (int i = 0; i < 3; i++) {
                int idx = tid + i * CONV_THREADS;
                if (idx < (BM + 2) * 4) {
                    int row = idx >> 2, u = idx & 3;
                    int t = t0 + row - 1;
                    int ok = (t >= 0 && t < T);
                    int tc = ok ? t : 0;
                    cp16(pb + (uint32_t)((row * XS + u * 8) * 2),
                         xp + ((size_t)(b * T + tc) * D + c0 + u * 8),
                         ok ? 16 : 0);
                }
            }
        }
        // W plane: [tap][k 0..31][n 0..127], 1536 16B vectors
        const uint32_t wbsm = stb + (uint32_t)(2 * X_PLANE);
#pragma unroll
        for (int i = 0; i < 6; i++) {
            int idx = tid + i * CONV_THREADS;
            int r = idx >> 4, u = idx & 15;        // r = tap*32+k
            int tap = r >> 5, k = r & 31;
            cp16(wbsm + (uint32_t)((r * WS + u * 8) * 2),
                 w + ((size_t)(tap * D + c0 + k) * D + n0 + u * 8), 16);
        }
        asm volatile("cp.async.commit_group;");
    };

    load_chunk(0, 0);

#pragma unroll 1
    for (int it = 0; it < NCHUNK; it++) {
        const int st = it & 1;
        if (it + 1 < NCHUNK) {
            load_chunk(st ^ 1, (it + 1) * BK);
            asm volatile("cp.async.wait_group 1;");
        } else {
            asm volatile("cp.async.wait_group 0;");
        }
        __syncthreads();

        const uint32_t abase = sb + (uint32_t)(st * STAGE) + a_off;
        const uint32_t bbase = sb + (uint32_t)(st * STAGE) + b_off;

#pragma unroll
        for (int tap = 0; tap < KW; tap++) {
#pragma unroll
            for (int ks = 0; ks < 2; ks++) {
                uint32_t ah[2][4], al[2][4];
#pragma unroll
                for (int mt = 0; mt < 2; mt++) {
                    uint32_t addr = abase + (uint32_t)((mt * 16 + tap) * XS * 2 + ks * 32);
                    asm volatile(
                        "ldmatrix.sync.aligned.m8n8.x4.shared.b16 {%0,%1,%2,%3}, [%4];"
                        : "=r"(ah[mt][0]), "=r"(ah[mt][1]), "=r"(ah[mt][2]), "=r"(ah[mt][3])
                        : "r"(addr));
                    asm volatile(
                        "ldmatrix.sync.aligned.m8n8.x4.shared.b16 {%0,%1,%2,%3}, [%4];"
                        : "=r"(al[mt][0]), "=r"(al[mt][1]), "=r"(al[mt][2]), "=r"(al[mt][3])
                        : "r"(addr + (uint32_t)X_PLANE));
                }
                uint32_t bf[4][4];
#pragma unroll
                for (int q = 0; q < 4; q++) {
                    uint32_t addr = bbase +
                        (uint32_t)((tap * 32 + ks * 16) * WS * 2 + q * 32);
                    asm volatile(
                        "ldmatrix.sync.aligned.m8n8.x4.trans.shared.b16 {%0,%1,%2,%3}, [%4];"
                        : "=r"(bf[q][0]), "=r"(bf[q][1]), "=r"(bf[q][2]), "=r"(bf[q][3])
                        : "r"(addr));
                }
#pragma unroll
                for (int mt = 0; mt < 2; mt++)
#pragma unroll
                    for (int nt = 0; nt < 8; nt++) {
                        int q = nt >> 1, h = (nt & 1) * 2;
#define MMA_ACC(A0,A1,A2,A3,B0,B1)                                             \
                        asm volatile(                                          \
                            "mma.sync.aligned.m16n8k16.row.col.f32.f16.f16.f32 " \
                            "{%0,%1,%2,%3}, {%4,%5,%6,%7}, {%8,%9}, {%0,%1,%2,%3};" \
                            : "+f"(c[mt][nt][0]), "+f"(c[mt][nt][1]),          \
                              "+f"(c[mt][nt][2]), "+f"(c[mt][nt][3])           \
                            : "r"(A0), "r"(A1), "r"(A2), "r"(A3), "r"(B0), "r"(B1))
                        MMA_ACC(ah[mt][0], ah[mt][1], ah[mt][2], ah[mt][3],
                                bf[q][h], bf[q][h + 1]);
                        MMA_ACC(al[mt][0], al[mt][1], al[mt][2], al[mt][3],
                                bf[q][h], bf[q][h + 1]);
#undef MMA_ACC
                    }
            }
        }
        __syncthreads();
    }

    // ---- epilogue: bias + relu, fp32 store ----
    const int gid = lane >> 2, tig = lane & 3;
#pragma unroll
    for (int mt = 0; mt < 2; mt++) {
        int row0 = t0 + wm * 32 + mt * 16 + gid;
#pragma unroll
        for (int nt = 0; nt < 8; nt++) {
            int col = n0 + wn * 64 + nt * 8 + tig * 2;
            float bx = bias[col], by = bias[col + 1];
            float2 o0, o1;
            o0.x = fmaxf(c[mt][nt][0] + bx, 0.f);
            o0.y = fmaxf(c[mt][nt][1] + by, 0.f);
            o1.x = fmaxf(c[mt][nt][2] + bx, 0.f);
            o1.y = fmaxf(c[mt][nt][3] + by, 0.f);
            *reinterpret_cast<float2*>(y + ((size_t)(b * T + row0)) * D + col) = o0;
            *reinterpret_cast<float2*>(y + ((size_t)(b * T + row0 + 8)) * D + col) = o1;
        }
    }
}

// ================= fp32 -> fp16 hi/lo split =================
__global__ void __launch_bounds__(256)
cvt_split_kernel(const float4* __restrict__ x, uint2* __restrict__ hi,
                 uint2* __restrict__ lo, int n4) {
    int i = blockIdx.x * 256 + threadIdx.x;
    if (i < n4) {
        float4 v = x[i];
        __half hx, lx, hy, ly, hz, lz, hw, lw;
        split1h(v.x, hx, lx); split1h(v.y, hy, ly);
        split1h(v.z, hz, lz); split1h(v.w, hw, lw);
        __half2 h0 = {hx, hy}, h1 = {hz, hw};
        __half2 l0 = {lx, ly}, l1 = {lz, lw};
        uint2 oh, ol;
        oh.x = reinterpret_cast<const unsigned&>(h0);
        oh.y = reinterpret_cast<const unsigned&>(h1);
        ol.x = reinterpret_cast<const unsigned&>(l0);
        ol.y = reinterpret_cast<const unsigned&>(l1);
        hi[i] = oh;
        lo[i] = ol;
    }
}

// ================= fp32 -> fp16 (single plane, for weights) =================
__global__ void __launch_bounds__(256)
cvt_half_kernel(const float4* __restrict__ x, uint2* __restrict__ y, int n4) {
    int i = blockIdx.x * 256 + threadIdx.x;
    if (i < n4) {
        float4 v = x[i];
        __half2 a = __floats2half2_rn(v.x, v.y);
        __half2 b = __floats2half2_rn(v.z, v.w);
        uint2 o;
        o.x = reinterpret_cast<const unsigned&>(a);
        o.y = reinterpret_cast<const unsigned&>(b);
        y[i] = o;
    }
}

// ================= LayerNorm (fp32 in) -> fp16 hi/lo out =================
__global__ void __launch_bounds__(256)
ln_split_kernel(const float* __restrict__ x, const float* __restrict__ gw,
                const float* __restrict__ gb, __half* __restrict__ yh,
                __half* __restrict__ yl) {
    const int row  = blockIdx.x * 8 + (threadIdx.x >> 5);
    const int lane = threadIdx.x & 31;
    const float4* xr = reinterpret_cast<const float4*>(x) + (size_t)row * (D / 4);
    float4 v[4];
    float s = 0.f, sq = 0.f;
#pragma unroll
    for (int i = 0; i < 4; i++) {
        float4 t = xr[i * 32 + lane];
        v[i] = t;
        s  += t.x + t.y + t.z + t.w;
        sq += t.x * t.x + t.y * t.y + t.z * t.z + t.w * t.w;
    }
#pragma unroll
    for (int o = 16; o > 0; o >>= 1) {
        s  += __shfl_xor_sync(0xffffffffu, s, o);
        sq += __shfl_xor_sync(0xffffffffu, sq, o);
    }
    const float mu = s * (1.0f / D);
    const float rs = rsqrtf(sq * (1.0f / D) - mu * mu + 1e-5f);
    const float4* gv = reinterpret_cast<const float4*>(gw);
    const float4* bv = reinterpret_cast<const float4*>(gb);
    uint2* yhr = reinterpret_cast<uint2*>(yh + (size_t)row * D);
    uint2* ylr = reinterpret_cast<uint2*>(yl + (size_t)row * D);
#pragma unroll
    for (int i = 0; i < 4; i++) {
        float4 g = gv[i * 32 + lane], bb = bv[i * 32 + lane], t = v[i];
        float4 o;
        o.x = (t.x - mu) * rs * g.x + bb.x;
        o.y = (t.y - mu) * rs * g.y + bb.y;
        o.z = (t.z - mu) * rs * g.z + bb.z;
        o.w = (t.w - mu) * rs * g.w + bb.w;
        __half hx, lx, hy, ly, hz, lz, hw, lw;
        split1h(o.x, hx, lx); split1h(o.y, hy, ly);
        split1h(o.z, hz, lz); split1h(o.w, hw, lw);
        __half2 h0 = {hx, hy}, h1 = {hz, hw};
        __half2 l0 = {lx, ly}, l1 = {lz, lw};
        uint2 oh, ol;
        oh.x = reinterpret_cast<const unsigned&>(h0);
        oh.y = reinterpret_cast<const unsigned&>(h1);
        ol.x = reinterpret_cast<const unsigned&>(l0);
        ol.y = reinterpret_cast<const unsigned&>(l1);
        yhr[i * 32 + lane] = oh;
        ylr[i * 32 + lane] = ol;
    }
}

// ================= LayerNorm + linear(512->1) fused =================
__global__ void __launch_bounds__(256)
ln_linear_kernel(const float* __restrict__ x, const float* __restrict__ gw,
                 const float* __restrict__ gb, const float* __restrict__ lw,
                 const float* __restrict__ lb, float* __restrict__ dur_out) {
    const int row  = blockIdx.x * 8 + (threadIdx.x >> 5);
    const int lane = threadIdx.x & 31;
    const float4* xr = reinterpret_cast<const float4*>(x) + (size_t)row * (D / 4);
    float4 v[4];
    float s = 0.f, sq = 0.f;
#pragma unroll
    for (int i = 0; i < 4; i++) {
        float4 t = xr[i * 32 + lane];
        v[i] = t;
        s  += t.x + t.y + t.z + t.w;
        sq += t.x * t.x + t.y * t.y + t.z * t.z + t.w * t.w;
    }
#pragma unroll
    for (int o = 16; o > 0; o >>= 1) {
        s  += __shfl_xor_sync(0xffffffffu, s, o);
        sq += __shfl_xor_sync(0xffffffffu, sq, o);
    }
    const float mu = s * (1.0f / D);
    const float rs = rsqrtf(sq * (1.0f / D) - mu * mu + 1e-5f);
    const float4* gv = reinterpret_cast<const float4*>(gw);
    const float4* bv = reinterpret_cast<const float4*>(gb);
    const float4* wv = reinterpret_cast<const float4*>(lw);
    float dot = 0.f;
#pragma unroll
    for (int i = 0; i < 4; i++) {
        float4 g = gv[i * 32 + lane], bb = bv[i * 32 + lane];
        float4 w = wv[i * 32 + lane], t = v[i];
        dot += ((t.x - mu) * rs * g.x + bb.x) * w.x;
        dot += ((t.y - mu) * rs * g.y + bb.y) * w.y;
        dot += ((t.z - mu) * rs * g.z + bb.z) * w.z;
        dot += ((t.w - mu) * rs * g.w + bb.w) * w.w;
    }
#pragma unroll
    for (int o = 16; o > 0; o >>= 1)
        dot += __shfl_xor_sync(0xffffffffu, dot, o);
    if (lane == 0) dur_out[row] = dot + lb[0];
}

// ================= per-batch inclusive cumsum =================
__global__ void __launch_bounds__(T)
cumsum_kernel(const int* __restrict__ dur, int* __restrict__ cum) {
    __shared__ int s[T];
    const int b = blockIdx.x, t = threadIdx.x;
    s[t] = dur[b * T + t];
    __syncthreads();
#pragma unroll
    for (int off = 1; off < T; off <<= 1) {
        int add = (t >= off) ? s[t - off] : 0;
        __syncthreads();
        s[t] += add;
        __syncthreads();
    }
    cum[b * T + t] = s[t];
}

// ================= length-regulation gather =================
__global__ void __launch_bounds__(128)
expand_kernel(const float* __restrict__ enc, const int* __restrict__ cum,
              float* __restrict__ out, int max_len) {
    const int j    = blockIdx.x;
    const int b    = blockIdx.y;
    const int lane = threadIdx.x;
    const int* c = cum + b * T;
    const int total = c[T - 1];
    float4 v = make_float4(0.f, 0.f, 0.f, 0.f);
    if (j < total) {
        int lo = 0, hi = T - 1;
        while (lo < hi) {
            int mid = (lo + hi) >> 1;
            if (c[mid] > j) hi = mid; else lo = mid + 1;
        }
        v = reinterpret_cast<const float4*>(enc + (size_t)(b * T + lo) * D)[lane];
    }
    reinterpret_cast<float4*>(out + ((size_t)b * max_len + j) * D)[lane] = v;
}

extern "C" void kernel_launch(void* const* d_in, const int* in_sizes, int n_in,
                              void* d_out, int out_size) {
    const float* enc = (const float*)d_in[0];
    const int*   dur = (const int*)d_in[1];
    const float* w1  = (const float*)d_in[2];
    const float* b1  = (const float*)d_in[3];
    const float* g1  = (const float*)d_in[4];
    const float* be1 = (const float*)d_in[5];
    const float* w2  = (const float*)d_in[6];
    const float* b2  = (const float*)d_in[7];
    const float* g2  = (const float*)d_in[8];
    const float* be2 = (const float*)d_in[9];
    const float* lw  = (const float*)d_in[10];
    const float* lb  = (const float*)d_in[11];

    const int max_len = (out_size - B * T) / (B * D);
    float* out     = (float*)d_out;
    float* dur_out = out + (size_t)B * max_len * D;

    float* cbuf;    cudaGetSymbolAddress((void**)&cbuf, g_conv);
    __half *xh1, *xl1, *xh2, *xl2, *w1h, *w2h;
    cudaGetSymbolAddress((void**)&xh1, g_xh1);
    cudaGetSymbolAddress((void**)&xl1, g_xl1);
    cudaGetSymbolAddress((void**)&xh2, g_xh2);
    cudaGetSymbolAddress((void**)&xl2, g_xl2);
    cudaGetSymbolAddress((void**)&w1h, g_w1h);
    cudaGetSymbolAddress((void**)&w2h, g_w2h);
    int* cm;        cudaGetSymbolAddress((void**)&cm, g_cum);

    cudaFuncSetAttribute(conv_mma_kernel,
                         cudaFuncAttributeMaxDynamicSharedMemorySize, SM_TOTAL);

    // conversions: enc hi/lo split, weights single fp16 (native layouts)
    const int nx4 = (B * T * D) / 4;
    cvt_split_kernel<<<nx4 / 256, 256>>>((const float4*)enc, (uint2*)xh1, (uint2*)xl1, nx4);
    const int nw4 = (KW * D * D) / 4;
    cvt_half_kernel<<<(nw4 + 255) / 256, 256>>>((const float4*)w1, (uint2*)w1h, nw4);
    cvt_half_kernel<<<(nw4 + 255) / 256, 256>>>((const float4*)w2, (uint2*)w2h, nw4);

    dim3 cgrid(T / BM, D / BN, B);   // (8, 4, 32)
    conv_mma_kernel<<<cgrid, CONV_THREADS, SM_TOTAL>>>(xh1, xl1, w1h, b1, cbuf);
    ln_split_kernel<<<B * T / 8, 256>>>(cbuf, g1, be1, xh2, xl2);
    conv_mma_kernel<<<cgrid, CONV_THREADS, SM_TOTAL>>>(xh2, xl2, w2h, b2, cbuf);
    ln_linear_kernel<<<B * T / 8, 256>>>(cbuf, g2, be2, lw, lb, dur_out);

    cumsum_kernel<<<B, T>>>(dur, cm);
    dim3 egrid(max_len, B);
    expand_kernel<<<egrid, 128>>>(enc, cm, out, max_len);
}

// round 10
// speedup vs baseline: 4.6656x; 1.4270x over previous
#include <cuda_runtime.h>
#include <cuda_fp16.h>
#include <cstdint>

#define B  32
#define T  1024
#define D  512
#define KW 3

// ---- conv GEMM tiles ----
#define BM 128
#define BN 128
#define BK 32
#define XS 40            // Xs row stride in fp16 (80B: conflict-free for ldmatrix)
#define WS 136           // Ws row stride in fp16 (272B: conflict-free for ldmatrix.trans)
#define CONV_THREADS 256
#define NCHUNK (D / BK)  // 16

// dynamic smem: two stages, each = [X plane][W plane]
#define X_PLANE ((BM + 2) * XS * 2)          // 10400 B
#define W_PLANE (KW * BK * WS * 2)           // 26112 B
#define STAGE   (X_PLANE + W_PLANE)          // 36512 B
#define SM_TOTAL (2 * STAGE)                 // 73024 B

// ---- scratch (no runtime allocation allowed) ----
__device__ float  g_conv[(size_t)B * T * D];    // fp32 conv output
__device__ __half g_x1[(size_t)B * T * D];      // enc fp16
__device__ __half g_x2[(size_t)B * T * D];      // LN1 out fp16
__device__ __half g_w1h[KW * D * D];            // weights fp16 (native HIO)
__device__ __half g_w2h[KW * D * D];
__device__ int    g_cum[B * T];

__device__ __forceinline__ uint32_t smem_u32(const void* p) {
    uint32_t a;
    asm("{ .reg .u64 t; cvta.to.shared.u64 t, %1; cvt.u32.u64 %0, t; }" : "=r"(a) : "l"(p));
    return a;
}
__device__ __forceinline__ void cp16(uint32_t dst, const void* src, int szbytes) {
    asm volatile("cp.async.cg.shared.global [%0], [%1], 16, %2;"
                 :: "r"(dst), "l"(src), "r"(szbytes));
}

// ================= conv1d(k=3,SAME) + bias + relu, fp16 mma.sync ===========
__global__ void __launch_bounds__(CONV_THREADS)
conv_mma_kernel(const __half* __restrict__ x,
                const __half* __restrict__ w,   // [tap][c][n]
                const float* __restrict__ bias,
                float* __restrict__ y) {
    extern __shared__ __align__(16) char smem[];

    const int tid  = threadIdx.x;
    const int lane = tid & 31;
    const int wid  = tid >> 5;
    const int wm   = wid >> 1;     // 0..3 -> m offset wm*32
    const int wn   = wid & 1;      // 0..1 -> n offset wn*64
    const int t0   = blockIdx.x * BM;
    const int n0   = blockIdx.y * BN;
    const int b    = blockIdx.z;

    float c[2][8][4];
#pragma unroll
    for (int mt = 0; mt < 2; mt++)
#pragma unroll
        for (int nt = 0; nt < 8; nt++)
#pragma unroll
            for (int i = 0; i < 4; i++) c[mt][nt][i] = 0.f;

    const uint32_t sb = smem_u32(smem);
    const uint32_t a_off = (uint32_t)(((wm * 32 + (lane & 15)) * XS + (lane >> 4) * 8) * 2);
    const uint32_t b_off = (uint32_t)(X_PLANE +
                                      ((lane & 15) * WS + wn * 64 + (lane >> 4) * 8) * 2);

    // ---- async tile loader for chunk c0 into stage st ----
    auto load_chunk = [&](int st, int c0) {
        const uint32_t stb = sb + (uint32_t)(st * STAGE);
        // X plane: 520 16B vectors
#pragma unroll
        for (int i = 0; i < 3; i++) {
            int idx = tid + i * CONV_THREADS;
            if (idx < (BM + 2) * 4) {
                int row = idx >> 2, u = idx & 3;
                int t = t0 + row - 1;
                int ok = (t >= 0 && t < T);
                int tc = ok ? t : 0;
                cp16(stb + (uint32_t)((row * XS + u * 8) * 2),
                     x + ((size_t)(b * T + tc) * D + c0 + u * 8),
                     ok ? 16 : 0);
            }
        }
        // W plane: [tap][k 0..31][n 0..127], 1536 16B vectors
        const uint32_t wbsm = stb + (uint32_t)X_PLANE;
#pragma unroll
        for (int i = 0; i < 6; i++) {
            int idx = tid + i * CONV_THREADS;
            int r = idx >> 4, u = idx & 15;        // r = tap*32+k
            int tap = r >> 5, k = r & 31;
            cp16(wbsm + (uint32_t)((r * WS + u * 8) * 2),
                 w + ((size_t)(tap * D + c0 + k) * D + n0 + u * 8), 16);
        }
        asm volatile("cp.async.commit_group;");
    };

    load_chunk(0, 0);

#pragma unroll 1
    for (int it = 0; it < NCHUNK; it++) {
        const int st = it & 1;
        if (it + 1 < NCHUNK) {
            load_chunk(st ^ 1, (it + 1) * BK);
            asm volatile("cp.async.wait_group 1;");
        } else {
            asm volatile("cp.async.wait_group 0;");
        }
        __syncthreads();

        const uint32_t abase = sb + (uint32_t)(st * STAGE) + a_off;
        const uint32_t bbase = sb + (uint32_t)(st * STAGE) + b_off;

#pragma unroll
        for (int tap = 0; tap < KW; tap++) {
#pragma unroll
            for (int ks = 0; ks < 2; ks++) {
                uint32_t a[2][4];
#pragma unroll
                for (int mt = 0; mt < 2; mt++) {
                    uint32_t addr = abase + (uint32_t)((mt * 16 + tap) * XS * 2 + ks * 32);
                    asm volatile(
                        "ldmatrix.sync.aligned.m8n8.x4.shared.b16 {%0,%1,%2,%3}, [%4];"
                        : "=r"(a[mt][0]), "=r"(a[mt][1]), "=r"(a[mt][2]), "=r"(a[mt][3])
                        : "r"(addr));
                }
                uint32_t bf[4][4];
#pragma unroll
                for (int q = 0; q < 4; q++) {
                    uint32_t addr = bbase +
                        (uint32_t)((tap * 32 + ks * 16) * WS * 2 + q * 32);
                    asm volatile(
                        "ldmatrix.sync.aligned.m8n8.x4.trans.shared.b16 {%0,%1,%2,%3}, [%4];"
                        : "=r"(bf[q][0]), "=r"(bf[q][1]), "=r"(bf[q][2]), "=r"(bf[q][3])
                        : "r"(addr));
                }
#pragma unroll
                for (int mt = 0; mt < 2; mt++)
#pragma unroll
                    for (int nt = 0; nt < 8; nt++) {
                        int q = nt >> 1, h = (nt & 1) * 2;
                        asm volatile(
                            "mma.sync.aligned.m16n8k16.row.col.f32.f16.f16.f32 "
                            "{%0,%1,%2,%3}, {%4,%5,%6,%7}, {%8,%9}, {%0,%1,%2,%3};"
                            : "+f"(c[mt][nt][0]), "+f"(c[mt][nt][1]),
                              "+f"(c[mt][nt][2]), "+f"(c[mt][nt][3])
                            : "r"(a[mt][0]), "r"(a[mt][1]), "r"(a[mt][2]), "r"(a[mt][3]),
                              "r"(bf[q][h]), "r"(bf[q][h + 1]));
                    }
            }
        }
        __syncthreads();
    }

    // ---- epilogue: bias + relu, fp32 store ----
    const int gid = lane >> 2, tig = lane & 3;
#pragma unroll
    for (int mt = 0; mt < 2; mt++) {
        int row0 = t0 + wm * 32 + mt * 16 + gid;
#pragma unroll
        for (int nt = 0; nt < 8; nt++) {
            int col = n0 + wn * 64 + nt * 8 + tig * 2;
            float bx = bias[col], by = bias[col + 1];
            float2 o0, o1;
            o0.x = fmaxf(c[mt][nt][0] + bx, 0.f);
            o0.y = fmaxf(c[mt][nt][1] + by, 0.f);
            o1.x = fmaxf(c[mt][nt][2] + bx, 0.f);
            o1.y = fmaxf(c[mt][nt][3] + by, 0.f);
            *reinterpret_cast<float2*>(y + ((size_t)(b * T + row0)) * D + col) = o0;
            *reinterpret_cast<float2*>(y + ((size_t)(b * T + row0 + 8)) * D + col) = o1;
        }
    }
}

// ================= fp32 -> fp16 =================
__global__ void __launch_bounds__(256)
cvt_half_kernel(const float4* __restrict__ x, uint2* __restrict__ y, int n4) {
    int i = blockIdx.x * 256 + threadIdx.x;
    if (i < n4) {
        float4 v = x[i];
        __half2 a = __floats2half2_rn(v.x, v.y);
        __half2 b = __floats2half2_rn(v.z, v.w);
        uint2 o;
        o.x = reinterpret_cast<const unsigned&>(a);
        o.y = reinterpret_cast<const unsigned&>(b);
        y[i] = o;
    }
}

// ================= LayerNorm (fp32 in) -> fp16 out =================
__global__ void __launch_bounds__(256)
ln_half_kernel(const float* __restrict__ x, const float* __restrict__ gw,
               const float* __restrict__ gb, __half* __restrict__ y) {
    const int row  = blockIdx.x * 8 + (threadIdx.x >> 5);
    const int lane = threadIdx.x & 31;
    const float4* xr = reinterpret_cast<const float4*>(x) + (size_t)row * (D / 4);
    float4 v[4];
    float s = 0.f, sq = 0.f;
#pragma unroll
    for (int i = 0; i < 4; i++) {
        float4 t = xr[i * 32 + lane];
        v[i] = t;
        s  += t.x + t.y + t.z + t.w;
        sq += t.x * t.x + t.y * t.y + t.z * t.z + t.w * t.w;
    }
#pragma unroll
    for (int o = 16; o > 0; o >>= 1) {
        s  += __shfl_xor_sync(0xffffffffu, s, o);
        sq += __shfl_xor_sync(0xffffffffu, sq, o);
    }
    const float mu = s * (1.0f / D);
    const float rs = rsqrtf(sq * (1.0f / D) - mu * mu + 1e-5f);
    const float4* gv = reinterpret_cast<const float4*>(gw);
    const float4* bv = reinterpret_cast<const float4*>(gb);
    uint2* yr = reinterpret_cast<uint2*>(y + (size_t)row * D);
#pragma unroll
    for (int i = 0; i < 4; i++) {
        float4 g = gv[i * 32 + lane], bb = bv[i * 32 + lane], t = v[i];
        float4 o;
        o.x = (t.x - mu) * rs * g.x + bb.x;
        o.y = (t.y - mu) * rs * g.y + bb.y;
        o.z = (t.z - mu) * rs * g.z + bb.z;
        o.w = (t.w - mu) * rs * g.w + bb.w;
        __half2 p0 = __floats2half2_rn(o.x, o.y);
        __half2 p1 = __floats2half2_rn(o.z, o.w);
        uint2 u;
        u.x = reinterpret_cast<const unsigned&>(p0);
        u.y = reinterpret_cast<const unsigned&>(p1);
        yr[i * 32 + lane] = u;
    }
}

// ================= LayerNorm + linear(512->1) fused =================
__global__ void __launch_bounds__(256)
ln_linear_kernel(const float* __restrict__ x, const float* __restrict__ gw,
                 const float* __restrict__ gb, const float* __restrict__ lw,
                 const float* __restrict__ lb, float* __restrict__ dur_out) {
    const int row  = blockIdx.x * 8 + (threadIdx.x >> 5);
    const int lane = threadIdx.x & 31;
    const float4* xr = reinterpret_cast<const float4*>(x) + (size_t)row * (D / 4);
    float4 v[4];
    float s = 0.f, sq = 0.f;
#pragma unroll
    for (int i = 0; i < 4; i++) {
        float4 t = xr[i * 32 + lane];
        v[i] = t;
        s  += t.x + t.y + t.z + t.w;
        sq += t.x * t.x + t.y * t.y + t.z * t.z + t.w * t.w;
    }
#pragma unroll
    for (int o = 16; o > 0; o >>= 1) {
        s  += __shfl_xor_sync(0xffffffffu, s, o);
        sq += __shfl_xor_sync(0xffffffffu, sq, o);
    }
    const float mu = s * (1.0f / D);
    const float rs = rsqrtf(sq * (1.0f / D) - mu * mu + 1e-5f);
    const float4* gv = reinterpret_cast<const float4*>(gw);
    const float4* bv = reinterpret_cast<const float4*>(gb);
    const float4* wv = reinterpret_cast<const float4*>(lw);
    float dot = 0.f;
#pragma unroll
    for (int i = 0; i < 4; i++) {
        float4 g = gv[i * 32 + lane], bb = bv[i * 32 + lane];
        float4 w = wv[i * 32 + lane], t = v[i];
        dot += ((t.x - mu) * rs * g.x + bb.x) * w.x;
        dot += ((t.y - mu) * rs * g.y + bb.y) * w.y;
        dot += ((t.z - mu) * rs * g.z + bb.z) * w.z;
        dot += ((t.w - mu) * rs * g.w + bb.w) * w.w;
    }
#pragma unroll
    for (int o = 16; o > 0; o >>= 1)
        dot += __shfl_xor_sync(0xffffffffu, dot, o);
    if (lane == 0) dur_out[row] = dot + lb[0];
}

// ================= per-batch inclusive cumsum =================
__global__ void __launch_bounds__(T)
cumsum_kernel(const int* __restrict__ dur, int* __restrict__ cum) {
    __shared__ int s[T];
    const int b = blockIdx.x, t = threadIdx.x;
    s[t] = dur[b * T + t];
    __syncthreads();
#pragma unroll
    for (int off = 1; off < T; off <<= 1) {
        int add = (t >= off) ? s[t - off] : 0;
        __syncthreads();
        s[t] += add;
        __syncthreads();
    }
    cum[b * T + t] = s[t];
}

// ================= length-regulation gather =================
__global__ void __launch_bounds__(128)
expand_kernel(const float* __restrict__ enc, const int* __restrict__ cum,
              float* __restrict__ out, int max_len) {
    const int j    = blockIdx.x;
    const int b    = blockIdx.y;
    const int lane = threadIdx.x;
    const int* c = cum + b * T;
    const int total = c[T - 1];
    float4 v = make_float4(0.f, 0.f, 0.f, 0.f);
    if (j < total) {
        int lo = 0, hi = T - 1;
        while (lo < hi) {
            int mid = (lo + hi) >> 1;
            if (c[mid] > j) hi = mid; else lo = mid + 1;
        }
        v = reinterpret_cast<const float4*>(enc + (size_t)(b * T + lo) * D)[lane];
    }
    reinterpret_cast<float4*>(out + ((size_t)b * max_len + j) * D)[lane] = v;
}

extern "C" void kernel_launch(void* const* d_in, const int* in_sizes, int n_in,
                              void* d_out, int out_size) {
    const float* enc = (const float*)d_in[0];
    const int*   dur = (const int*)d_in[1];
    const float* w1  = (const float*)d_in[2];
    const float* b1  = (const float*)d_in[3];
    const float* g1  = (const float*)d_in[4];
    const float* be1 = (const float*)d_in[5];
    const float* w2  = (const float*)d_in[6];
    const float* b2  = (const float*)d_in[7];
    const float* g2  = (const float*)d_in[8];
    const float* be2 = (const float*)d_in[9];
    const float* lw  = (const float*)d_in[10];
    const float* lb  = (const float*)d_in[11];

    const int max_len = (out_size - B * T) / (B * D);
    float* out     = (float*)d_out;
    float* dur_out = out + (size_t)B * max_len * D;

    float* cbuf;    cudaGetSymbolAddress((void**)&cbuf, g_conv);
    __half *x1, *x2, *w1h, *w2h;
    cudaGetSymbolAddress((void**)&x1, g_x1);
    cudaGetSymbolAddress((void**)&x2, g_x2);
    cudaGetSymbolAddress((void**)&w1h, g_w1h);
    cudaGetSymbolAddress((void**)&w2h, g_w2h);
    int* cm;        cudaGetSymbolAddress((void**)&cm, g_cum);

    cudaFuncSetAttribute(conv_mma_kernel,
                         cudaFuncAttributeMaxDynamicSharedMemorySize, SM_TOTAL);

    // conversions: enc + weights to fp16 (native layouts)
    const int nx4 = (B * T * D) / 4;
    cvt_half_kernel<<<nx4 / 256, 256>>>((const float4*)enc, (uint2*)x1, nx4);
    const int nw4 = (KW * D * D) / 4;
    cvt_half_kernel<<<(nw4 + 255) / 256, 256>>>((const float4*)w1, (uint2*)w1h, nw4);
    cvt_half_kernel<<<(nw4 + 255) / 256, 256>>>((const float4*)w2, (uint2*)w2h, nw4);

    dim3 cgrid(T / BM, D / BN, B);   // (8, 4, 32)
    conv_mma_kernel<<<cgrid, CONV_THREADS, SM_TOTAL>>>(x1, w1h, b1, cbuf);
    ln_half_kernel<<<B * T / 8, 256>>>(cbuf, g1, be1, x2);
    conv_mma_kernel<<<cgrid, CONV_THREADS, SM_TOTAL>>>(x2, w2h, b2, cbuf);
    ln_linear_kernel<<<B * T / 8, 256>>>(cbuf, g2, be2, lw, lb, dur_out);

    cumsum_kernel<<<B, T>>>(dur, cm);
    dim3 egrid(max_len, B);
    expand_kernel<<<egrid, 128>>>(enc, cm, out, max_len);
}